// round 1
// baseline (speedup 1.0000x reference)
#include <cuda_runtime.h>
#include <math.h>

// Problem constants
#define Bc 4
#define Nc 8192
#define Ec 128
#define Hc 4
#define Dc 32
#define PADc 16
#define Wc 33
#define BHc 16
#define Mc (Bc * Nc)   // 32768 rows

// Scratch (device globals: no allocation allowed in kernel_launch)
__device__ float g_Q[(size_t)BHc * Nc * Dc];     // (B,H,N,D)
__device__ float g_K[(size_t)BHc * Nc * Dc];
__device__ float g_V[(size_t)BHc * Nc * Dc];
__device__ float g_ctx[(size_t)Mc * Ec];          // (B,N,E)

// ---------------------------------------------------------------------------
// Kernel 1: fused QKV projection.  out = q @ W.T + b, scattered to (B,H,N,D).
// Tile: 128 rows x 128 cols, K in steps of 16. 256 threads, 8x8 per thread.
// grid = (Mc/128, 3)  [y selects Q/K/V weight]
// ---------------------------------------------------------------------------
__global__ __launch_bounds__(256) void qkv_gemm(
    const float* __restrict__ q,
    const float* __restrict__ Wq, const float* __restrict__ bq,
    const float* __restrict__ Wk, const float* __restrict__ bk,
    const float* __restrict__ Wv, const float* __restrict__ bv)
{
    const int which = blockIdx.y;
    const float* __restrict__ Wm = (which == 0) ? Wq : ((which == 1) ? Wk : Wv);
    const float* __restrict__ bm = (which == 0) ? bq : ((which == 1) ? bk : bv);
    float* __restrict__ outp = (which == 0) ? g_Q : ((which == 1) ? g_K : g_V);

    __shared__ __align__(16) float As[16][132];  // [k][m], padded
    __shared__ __align__(16) float Ws[16][132];  // [k][e], padded

    const int tid = threadIdx.x;
    const int tx = tid & 15;       // col group
    const int ty = tid >> 4;       // row group
    const int m0 = blockIdx.x * 128;

    float acc[8][8];
#pragma unroll
    for (int i = 0; i < 8; i++)
#pragma unroll
        for (int j = 0; j < 8; j++) acc[i][j] = 0.f;

    for (int k0 = 0; k0 < 128; k0 += 16) {
#pragma unroll
        for (int i = 0; i < 2; i++) {
            int li = tid + i * 256;      // 0..511
            int r  = li >> 2;            // row (0..127)
            int c4 = (li & 3) * 4;       // k sub-offset
            float4 va = *(const float4*)(q  + (size_t)(m0 + r) * 128 + k0 + c4);
            As[c4 + 0][r] = va.x; As[c4 + 1][r] = va.y;
            As[c4 + 2][r] = va.z; As[c4 + 3][r] = va.w;
            float4 vw = *(const float4*)(Wm + (size_t)r * 128 + k0 + c4);
            Ws[c4 + 0][r] = vw.x; Ws[c4 + 1][r] = vw.y;
            Ws[c4 + 2][r] = vw.z; Ws[c4 + 3][r] = vw.w;
        }
        __syncthreads();

#pragma unroll
        for (int k = 0; k < 16; k++) {
            float a[8], b[8];
            *(float4*)(a)     = *(const float4*)&As[k][ty * 8];
            *(float4*)(a + 4) = *(const float4*)&As[k][ty * 8 + 4];
            *(float4*)(b)     = *(const float4*)&Ws[k][tx * 8];
            *(float4*)(b + 4) = *(const float4*)&Ws[k][tx * 8 + 4];
#pragma unroll
            for (int i = 0; i < 8; i++)
#pragma unroll
                for (int j = 0; j < 8; j++)
                    acc[i][j] = fmaf(a[i], b[j], acc[i][j]);
        }
        __syncthreads();
    }

    // Epilogue: add bias, scatter to (B,H,N,D)
#pragma unroll
    for (int i = 0; i < 8; i++) {
        int m = m0 + ty * 8 + i;
        int b = m >> 13;        // / 8192
        int n = m & 8191;
#pragma unroll
        for (int j = 0; j < 8; j++) {
            int e = tx * 8 + j;
            int h = e >> 5;
            int d = e & 31;
            outp[((size_t)(b * Hc + h) * Nc + n) * Dc + d] = acc[i][j] + bm[e];
        }
    }
}

// ---------------------------------------------------------------------------
// Kernel 2: sliding-window attention for one (b,h) and a 128-query tile.
// Reference semantics: positions outside [0,N) contribute score = 0 (NOT -inf)
// and zero V rows (zero-padding), and they DO participate in the softmax.
// grid = (N/128, BH), block = 128 threads (one thread per query).
// ---------------------------------------------------------------------------
__global__ __launch_bounds__(128) void attn_kernel(float* __restrict__ probs_out)
{
    const int tile = blockIdx.x;     // 0..63
    const int bh   = blockIdx.y;     // 0..15
    const int tid  = threadIdx.x;    // 0..127

    // window rows [g0, g0+160)
    const int g0 = tile * 128 - PADc;

    __shared__ float Ks[160 * 33];
    __shared__ float Vs[160 * 33];

    const float* __restrict__ Kg = g_K + (size_t)bh * Nc * Dc;
    const float* __restrict__ Vg = g_V + (size_t)bh * Nc * Dc;

    for (int i = tid; i < 160 * 32; i += 128) {
        int r = i >> 5;
        int c = i & 31;
        int gr = g0 + r;
        float kv = 0.f, vv = 0.f;
        if (gr >= 0 && gr < Nc) {
            kv = Kg[(size_t)gr * 32 + c];
            vv = Vg[(size_t)gr * 32 + c];
        }
        Ks[r * 33 + c] = kv;
        Vs[r * 33 + c] = vv;
    }
    __syncthreads();

    const int n = tile * 128 + tid;

    // Q row into registers
    float qreg[32];
    const float* __restrict__ Qg = g_Q + ((size_t)bh * Nc + n) * 32;
#pragma unroll
    for (int i = 0; i < 8; i++) {
        float4 v = *(const float4*)(Qg + i * 4);
        qreg[i * 4 + 0] = v.x; qreg[i * 4 + 1] = v.y;
        qreg[i * 4 + 2] = v.z; qreg[i * 4 + 3] = v.w;
    }

    // Scores: window pos w -> smem row (tid + w)
    const float scale = 0.17677669529663687f;  // 1/sqrt(32)
    float sc[33];
#pragma unroll
    for (int w = 0; w < 33; w++) {
        const float* kr = &Ks[(tid + w) * 33];
        float s = 0.f;
#pragma unroll
        for (int d = 0; d < 32; d++) s = fmaf(qreg[d], kr[d], s);
        sc[w] = s * scale;
    }

    // Softmax over all 33 positions (padding included, matching reference)
    float m = sc[0];
#pragma unroll
    for (int w = 1; w < 33; w++) m = fmaxf(m, sc[w]);
    float ssum = 0.f;
#pragma unroll
    for (int w = 0; w < 33; w++) {
        sc[w] = __expf(sc[w] - m);
        ssum += sc[w];
    }
    const float rinv = 1.f / ssum;

    // probs out: (B,H,N,W)
    float* __restrict__ pr = probs_out + ((size_t)bh * Nc + n) * Wc;
#pragma unroll
    for (int w = 0; w < 33; w++) pr[w] = sc[w] * rinv;

    // Context: sum_w p[w] * V[win row]
    float ctx[32];
#pragma unroll
    for (int d = 0; d < 32; d++) ctx[d] = 0.f;
#pragma unroll
    for (int w = 0; w < 33; w++) {
        const float p = sc[w];
        const float* vr = &Vs[(tid + w) * 33];
#pragma unroll
        for (int d = 0; d < 32; d++) ctx[d] = fmaf(p, vr[d], ctx[d]);
    }

    // Write ctx to (B,N,E)
    const int b = bh >> 2;
    const int h = bh & 3;
    float* __restrict__ cg = g_ctx + ((size_t)b * Nc + n) * Ec + h * 32;
#pragma unroll
    for (int i = 0; i < 8; i++) {
        float4 v;
        v.x = ctx[i * 4 + 0] * rinv;
        v.y = ctx[i * 4 + 1] * rinv;
        v.z = ctx[i * 4 + 2] * rinv;
        v.w = ctx[i * 4 + 3] * rinv;
        *(float4*)(cg + i * 4) = v;
    }
}

// ---------------------------------------------------------------------------
// Kernel 3: output projection.  out = ctx @ Wo.T + bo  -> d_out (B,N,E)
// ---------------------------------------------------------------------------
__global__ __launch_bounds__(256) void out_gemm(
    const float* __restrict__ Wo, const float* __restrict__ bo,
    float* __restrict__ outp)
{
    __shared__ __align__(16) float As[16][132];
    __shared__ __align__(16) float Ws[16][132];

    const int tid = threadIdx.x;
    const int tx = tid & 15;
    const int ty = tid >> 4;
    const int m0 = blockIdx.x * 128;

    float acc[8][8];
#pragma unroll
    for (int i = 0; i < 8; i++)
#pragma unroll
        for (int j = 0; j < 8; j++) acc[i][j] = 0.f;

    for (int k0 = 0; k0 < 128; k0 += 16) {
#pragma unroll
        for (int i = 0; i < 2; i++) {
            int li = tid + i * 256;
            int r  = li >> 2;
            int c4 = (li & 3) * 4;
            float4 va = *(const float4*)(g_ctx + (size_t)(m0 + r) * 128 + k0 + c4);
            As[c4 + 0][r] = va.x; As[c4 + 1][r] = va.y;
            As[c4 + 2][r] = va.z; As[c4 + 3][r] = va.w;
            float4 vw = *(const float4*)(Wo + (size_t)r * 128 + k0 + c4);
            Ws[c4 + 0][r] = vw.x; Ws[c4 + 1][r] = vw.y;
            Ws[c4 + 2][r] = vw.z; Ws[c4 + 3][r] = vw.w;
        }
        __syncthreads();

#pragma unroll
        for (int k = 0; k < 16; k++) {
            float a[8], b[8];
            *(float4*)(a)     = *(const float4*)&As[k][ty * 8];
            *(float4*)(a + 4) = *(const float4*)&As[k][ty * 8 + 4];
            *(float4*)(b)     = *(const float4*)&Ws[k][tx * 8];
            *(float4*)(b + 4) = *(const float4*)&Ws[k][tx * 8 + 4];
#pragma unroll
            for (int i = 0; i < 8; i++)
#pragma unroll
                for (int j = 0; j < 8; j++)
                    acc[i][j] = fmaf(a[i], b[j], acc[i][j]);
        }
        __syncthreads();
    }

#pragma unroll
    for (int i = 0; i < 8; i++) {
        int m = m0 + ty * 8 + i;
#pragma unroll
        for (int j = 0; j < 8; j += 4) {
            int e = tx * 8 + j;
            float4 v;
            v.x = acc[i][j + 0] + bo[e + 0];
            v.y = acc[i][j + 1] + bo[e + 1];
            v.z = acc[i][j + 2] + bo[e + 2];
            v.w = acc[i][j + 3] + bo[e + 3];
            *(float4*)(outp + (size_t)m * 128 + e) = v;
        }
    }
}

// ---------------------------------------------------------------------------
extern "C" void kernel_launch(void* const* d_in, const int* in_sizes, int n_in,
                              void* d_out, int out_size)
{
    (void)in_sizes; (void)n_in; (void)out_size;
    const float* q  = (const float*)d_in[0];
    const float* Wq = (const float*)d_in[1];
    const float* bq = (const float*)d_in[2];
    const float* Wk = (const float*)d_in[3];
    const float* bk = (const float*)d_in[4];
    const float* Wv = (const float*)d_in[5];
    const float* bv = (const float*)d_in[6];
    const float* Wo = (const float*)d_in[7];
    const float* bo = (const float*)d_in[8];

    float* outp  = (float*)d_out;                         // (B,N,E)
    float* probs = outp + (size_t)Bc * Nc * Ec;           // (B,H,N,W)

    qkv_gemm<<<dim3(Mc / 128, 3), 256>>>(q, Wq, bq, Wk, bk, Wv, bv);
    attn_kernel<<<dim3(Nc / 128, BHc), 128>>>(probs);
    out_gemm<<<dim3(Mc / 128, 1), 256>>>(Wo, bo, outp);
}

// round 2
// speedup vs baseline: 1.8578x; 1.8578x over previous
#include <cuda_runtime.h>
#include <math.h>
#include <stdint.h>

// Problem constants
#define Bc 4
#define Nc 8192
#define Ec 128
#define Hc 4
#define Dc 32
#define PADc 16
#define Wc 33
#define BHc 16
#define Mc (Bc * Nc)   // 32768 rows

// Scratch (device globals: no allocation allowed in kernel_launch)
__device__ float g_Q[(size_t)BHc * Nc * Dc];     // (B,H,N,D)
__device__ float g_K[(size_t)BHc * Nc * Dc];
__device__ float g_V[(size_t)BHc * Nc * Dc];
__device__ float g_ctx[(size_t)Mc * Ec];          // (B,N,E)

__device__ __forceinline__ uint32_t f2tf32(float x) {
    uint32_t r;
    asm("cvt.rna.tf32.f32 %0, %1;" : "=r"(r) : "f"(x));
    return r;
}

__device__ __forceinline__ void mma_tf32(
    float& c0, float& c1, float& c2, float& c3,
    uint32_t a0, uint32_t a1, uint32_t a2, uint32_t a3,
    uint32_t b0, uint32_t b1)
{
    asm volatile(
        "mma.sync.aligned.m16n8k8.row.col.f32.tf32.tf32.f32 "
        "{%0,%1,%2,%3}, {%4,%5,%6,%7}, {%8,%9}, {%0,%1,%2,%3};\n"
        : "+f"(c0), "+f"(c1), "+f"(c2), "+f"(c3)
        : "r"(a0), "r"(a1), "r"(a2), "r"(a3), "r"(b0), "r"(b1));
}

// ---------------------------------------------------------------------------
// tf32 MMA GEMM core: C(128x128) = A(128x128) @ B(128x128)^T  (+bias)
// A row-major [m][k], B row-major [n][k] (i.e. W[e][k]), K chunked by 32.
// 256 threads = 8 warps; warp grid 4(M) x 2(N); warp tile 32x64.
// smem stride 36 => fragment LDS pattern (4*(lane>>2)+(lane&3)) is
// conflict-free across all 32 banks.
// ---------------------------------------------------------------------------
#define GEMM_MMA_BODY(A_PTR, B_PTR, EPILOGUE)                                   \
    __shared__ uint32_t As[128 * 36];                                           \
    __shared__ uint32_t Bs[128 * 36];                                           \
    const int tid  = threadIdx.x;                                               \
    const int wid  = tid >> 5;                                                  \
    const int lane = tid & 31;                                                  \
    const int wm   = wid >> 1;       /* 0..3 */                                 \
    const int wn   = wid & 1;        /* 0..1 */                                 \
    const int gr   = lane >> 2;      /* 0..7 */                                 \
    const int gc   = lane & 3;       /* 0..3 */                                 \
    const int m0   = blockIdx.x * 128;                                          \
    float acc[2][8][4];                                                         \
    _Pragma("unroll")                                                           \
    for (int i = 0; i < 2; i++)                                                 \
        _Pragma("unroll")                                                       \
        for (int j = 0; j < 8; j++)                                             \
            _Pragma("unroll")                                                   \
            for (int e = 0; e < 4; e++) acc[i][j][e] = 0.f;                     \
    for (int k0 = 0; k0 < 128; k0 += 32) {                                      \
        _Pragma("unroll")                                                       \
        for (int l = 0; l < 4; l++) {                                           \
            int li = tid + l * 256;                                             \
            int r  = li >> 3;                                                   \
            int c4 = (li & 7) * 4;                                              \
            float4 va = *(const float4*)(A_PTR + (size_t)(m0 + r) * 128 + k0 + c4); \
            As[r * 36 + c4 + 0] = f2tf32(va.x);                                 \
            As[r * 36 + c4 + 1] = f2tf32(va.y);                                 \
            As[r * 36 + c4 + 2] = f2tf32(va.z);                                 \
            As[r * 36 + c4 + 3] = f2tf32(va.w);                                 \
            float4 vb = *(const float4*)(B_PTR + (size_t)r * 128 + k0 + c4);    \
            Bs[r * 36 + c4 + 0] = f2tf32(vb.x);                                 \
            Bs[r * 36 + c4 + 1] = f2tf32(vb.y);                                 \
            Bs[r * 36 + c4 + 2] = f2tf32(vb.z);                                 \
            Bs[r * 36 + c4 + 3] = f2tf32(vb.w);                                 \
        }                                                                       \
        __syncthreads();                                                        \
        _Pragma("unroll")                                                       \
        for (int kk = 0; kk < 32; kk += 8) {                                    \
            uint32_t af[2][4];                                                  \
            _Pragma("unroll")                                                   \
            for (int i = 0; i < 2; i++) {                                       \
                int rbase = (wm * 32 + i * 16 + gr) * 36 + kk + gc;             \
                af[i][0] = As[rbase];                                           \
                af[i][1] = As[rbase + 8 * 36];                                  \
                af[i][2] = As[rbase + 4];                                       \
                af[i][3] = As[rbase + 8 * 36 + 4];                              \
            }                                                                   \
            uint32_t bf[8][2];                                                  \
            _Pragma("unroll")                                                   \
            for (int j = 0; j < 8; j++) {                                       \
                int nbase = (wn * 64 + j * 8 + gr) * 36 + kk + gc;              \
                bf[j][0] = Bs[nbase];                                           \
                bf[j][1] = Bs[nbase + 4];                                       \
            }                                                                   \
            _Pragma("unroll")                                                   \
            for (int i = 0; i < 2; i++)                                         \
                _Pragma("unroll")                                               \
                for (int j = 0; j < 8; j++)                                     \
                    mma_tf32(acc[i][j][0], acc[i][j][1], acc[i][j][2], acc[i][j][3], \
                             af[i][0], af[i][1], af[i][2], af[i][3],            \
                             bf[j][0], bf[j][1]);                               \
        }                                                                       \
        __syncthreads();                                                        \
    }                                                                           \
    EPILOGUE

// ---------------------------------------------------------------------------
// Kernel 1: fused QKV projection. out = q @ W.T + b, scattered to (B,H,N,D).
// grid = (256, 3)
// ---------------------------------------------------------------------------
__global__ __launch_bounds__(256, 2) void qkv_mma(
    const float* __restrict__ q,
    const float* __restrict__ Wq, const float* __restrict__ bq,
    const float* __restrict__ Wk, const float* __restrict__ bk,
    const float* __restrict__ Wv, const float* __restrict__ bv)
{
    const int which = blockIdx.y;
    const float* __restrict__ Wm = (which == 0) ? Wq : ((which == 1) ? Wk : Wv);
    const float* __restrict__ bm = (which == 0) ? bq : ((which == 1) ? bk : bv);
    float* __restrict__ outp = (which == 0) ? g_Q : ((which == 1) ? g_K : g_V);

    GEMM_MMA_BODY(q, Wm,
    {
        _Pragma("unroll")
        for (int i = 0; i < 2; i++) {
            _Pragma("unroll")
            for (int e2 = 0; e2 < 2; e2++) {   // row offset 0 / +8
                int m = m0 + wm * 32 + i * 16 + gr + e2 * 8;
                int b = m >> 13;
                int n = m & 8191;
                _Pragma("unroll")
                for (int j = 0; j < 8; j++) {
                    int col = wn * 64 + j * 8 + gc * 2;
                    int h = col >> 5;
                    int d = col & 31;
                    float2 v;
                    v.x = acc[i][j][e2 * 2 + 0] + bm[col];
                    v.y = acc[i][j][e2 * 2 + 1] + bm[col + 1];
                    *(float2*)(outp + ((size_t)(b * Hc + h) * Nc + n) * Dc + d) = v;
                }
            }
        }
    })
}

// ---------------------------------------------------------------------------
// Kernel 3: output projection. out = ctx @ Wo.T + bo -> d_out (B,N,E)
// ---------------------------------------------------------------------------
__global__ __launch_bounds__(256, 2) void out_mma(
    const float* __restrict__ Wo, const float* __restrict__ bo,
    float* __restrict__ outp)
{
    const float* __restrict__ ctxp = g_ctx;
    GEMM_MMA_BODY(ctxp, Wo,
    {
        _Pragma("unroll")
        for (int i = 0; i < 2; i++) {
            _Pragma("unroll")
            for (int e2 = 0; e2 < 2; e2++) {
                int m = m0 + wm * 32 + i * 16 + gr + e2 * 8;
                _Pragma("unroll")
                for (int j = 0; j < 8; j++) {
                    int col = wn * 64 + j * 8 + gc * 2;
                    float2 v;
                    v.x = acc[i][j][e2 * 2 + 0] + bo[col];
                    v.y = acc[i][j][e2 * 2 + 1] + bo[col + 1];
                    *(float2*)(outp + (size_t)m * 128 + col) = v;
                }
            }
        }
    })
}

// ---------------------------------------------------------------------------
// Kernel 2: sliding-window attention (unchanged from R1).
// Reference semantics: positions outside [0,N) contribute score = 0 (NOT -inf)
// and zero V rows, and they DO participate in the softmax.
// grid = (N/128, BH), block = 128 threads (one thread per query).
// ---------------------------------------------------------------------------
__global__ __launch_bounds__(128) void attn_kernel(float* __restrict__ probs_out)
{
    const int tile = blockIdx.x;
    const int bh   = blockIdx.y;
    const int tid  = threadIdx.x;

    const int g0 = tile * 128 - PADc;

    __shared__ float Ks[160 * 33];
    __shared__ float Vs[160 * 33];

    const float* __restrict__ Kg = g_K + (size_t)bh * Nc * Dc;
    const float* __restrict__ Vg = g_V + (size_t)bh * Nc * Dc;

    for (int i = tid; i < 160 * 32; i += 128) {
        int r = i >> 5;
        int c = i & 31;
        int gr = g0 + r;
        float kv = 0.f, vv = 0.f;
        if (gr >= 0 && gr < Nc) {
            kv = Kg[(size_t)gr * 32 + c];
            vv = Vg[(size_t)gr * 32 + c];
        }
        Ks[r * 33 + c] = kv;
        Vs[r * 33 + c] = vv;
    }
    __syncthreads();

    const int n = tile * 128 + tid;

    float qreg[32];
    const float* __restrict__ Qg = g_Q + ((size_t)bh * Nc + n) * 32;
#pragma unroll
    for (int i = 0; i < 8; i++) {
        float4 v = *(const float4*)(Qg + i * 4);
        qreg[i * 4 + 0] = v.x; qreg[i * 4 + 1] = v.y;
        qreg[i * 4 + 2] = v.z; qreg[i * 4 + 3] = v.w;
    }

    const float scale = 0.17677669529663687f;  // 1/sqrt(32)
    float sc[33];
#pragma unroll
    for (int w = 0; w < 33; w++) {
        const float* kr = &Ks[(tid + w) * 33];
        float s = 0.f;
#pragma unroll
        for (int d = 0; d < 32; d++) s = fmaf(qreg[d], kr[d], s);
        sc[w] = s * scale;
    }

    float m = sc[0];
#pragma unroll
    for (int w = 1; w < 33; w++) m = fmaxf(m, sc[w]);
    float ssum = 0.f;
#pragma unroll
    for (int w = 0; w < 33; w++) {
        sc[w] = __expf(sc[w] - m);
        ssum += sc[w];
    }
    const float rinv = 1.f / ssum;

    float* __restrict__ pr = probs_out + ((size_t)bh * Nc + n) * Wc;
#pragma unroll
    for (int w = 0; w < 33; w++) pr[w] = sc[w] * rinv;

    float ctx[32];
#pragma unroll
    for (int d = 0; d < 32; d++) ctx[d] = 0.f;
#pragma unroll
    for (int w = 0; w < 33; w++) {
        const float p = sc[w];
        const float* vr = &Vs[(tid + w) * 33];
#pragma unroll
        for (int d = 0; d < 32; d++) ctx[d] = fmaf(p, vr[d], ctx[d]);
    }

    const int b = bh >> 2;
    const int h = bh & 3;
    float* __restrict__ cg = g_ctx + ((size_t)b * Nc + n) * Ec + h * 32;
#pragma unroll
    for (int i = 0; i < 8; i++) {
        float4 v;
        v.x = ctx[i * 4 + 0] * rinv;
        v.y = ctx[i * 4 + 1] * rinv;
        v.z = ctx[i * 4 + 2] * rinv;
        v.w = ctx[i * 4 + 3] * rinv;
        *(float4*)(cg + i * 4) = v;
    }
}

// ---------------------------------------------------------------------------
extern "C" void kernel_launch(void* const* d_in, const int* in_sizes, int n_in,
                              void* d_out, int out_size)
{
    (void)in_sizes; (void)n_in; (void)out_size;
    const float* q  = (const float*)d_in[0];
    const float* Wq = (const float*)d_in[1];
    const float* bq = (const float*)d_in[2];
    const float* Wk = (const float*)d_in[3];
    const float* bk = (const float*)d_in[4];
    const float* Wv = (const float*)d_in[5];
    const float* bv = (const float*)d_in[6];
    const float* Wo = (const float*)d_in[7];
    const float* bo = (const float*)d_in[8];

    float* outp  = (float*)d_out;                         // (B,N,E)
    float* probs = outp + (size_t)Bc * Nc * Ec;           // (B,H,N,W)

    qkv_mma<<<dim3(Mc / 128, 3), 256>>>(q, Wq, bq, Wk, bk, Wv, bv);
    attn_kernel<<<dim3(Nc / 128, BHc), 128>>>(probs);
    out_mma<<<dim3(Mc / 128, 1), 256>>>(Wo, bo, outp);
}

// round 3
// speedup vs baseline: 2.3137x; 1.2454x over previous
#include <cuda_runtime.h>
#include <math.h>
#include <stdint.h>

// Problem constants
#define Bc 4
#define Nc 8192
#define Ec 128
#define Hc 4
#define Dc 32
#define PADc 16
#define Wc 33
#define BHc 16
#define Mc (Bc * Nc)   // 32768 rows

// Scratch (device globals: no allocation allowed in kernel_launch)
__device__ float g_Q[(size_t)BHc * Nc * Dc];     // (B,H,N,D)
__device__ float g_K[(size_t)BHc * Nc * Dc];
__device__ float g_V[(size_t)BHc * Nc * Dc];
__device__ float g_ctx[(size_t)Mc * Ec];          // (B,N,E)

__device__ __forceinline__ uint32_t f2tf32(float x) {
    uint32_t r;
    asm("cvt.rna.tf32.f32 %0, %1;" : "=r"(r) : "f"(x));
    return r;
}

__device__ __forceinline__ void mma_tf32(
    float& c0, float& c1, float& c2, float& c3,
    uint32_t a0, uint32_t a1, uint32_t a2, uint32_t a3,
    uint32_t b0, uint32_t b1)
{
    asm volatile(
        "mma.sync.aligned.m16n8k8.row.col.f32.tf32.tf32.f32 "
        "{%0,%1,%2,%3}, {%4,%5,%6,%7}, {%8,%9}, {%0,%1,%2,%3};\n"
        : "+f"(c0), "+f"(c1), "+f"(c2), "+f"(c3)
        : "r"(a0), "r"(a1), "r"(a2), "r"(a3), "r"(b0), "r"(b1));
}

// ---------------------------------------------------------------------------
// tf32 MMA GEMM core: C(128x128) = A(128x128) @ B(128x128)^T  (+bias)
// 256 threads = 8 warps; warp grid 4(M) x 2(N); warp tile 32x64.
// ---------------------------------------------------------------------------
#define GEMM_MMA_BODY(A_PTR, B_PTR, EPILOGUE)                                   \
    __shared__ uint32_t As[128 * 36];                                           \
    __shared__ uint32_t Bs[128 * 36];                                           \
    const int tid  = threadIdx.x;                                               \
    const int wid  = tid >> 5;                                                  \
    const int lane = tid & 31;                                                  \
    const int wm   = wid >> 1;       /* 0..3 */                                 \
    const int wn   = wid & 1;        /* 0..1 */                                 \
    const int gr   = lane >> 2;      /* 0..7 */                                 \
    const int gc   = lane & 3;       /* 0..3 */                                 \
    const int m0   = blockIdx.x * 128;                                          \
    float acc[2][8][4];                                                         \
    _Pragma("unroll")                                                           \
    for (int i = 0; i < 2; i++)                                                 \
        _Pragma("unroll")                                                       \
        for (int j = 0; j < 8; j++)                                             \
            _Pragma("unroll")                                                   \
            for (int e = 0; e < 4; e++) acc[i][j][e] = 0.f;                     \
    for (int k0 = 0; k0 < 128; k0 += 32) {                                      \
        _Pragma("unroll")                                                       \
        for (int l = 0; l < 4; l++) {                                           \
            int li = tid + l * 256;                                             \
            int r  = li >> 3;                                                   \
            int c4 = (li & 7) * 4;                                              \
            float4 va = *(const float4*)(A_PTR + (size_t)(m0 + r) * 128 + k0 + c4); \
            As[r * 36 + c4 + 0] = f2tf32(va.x);                                 \
            As[r * 36 + c4 + 1] = f2tf32(va.y);                                 \
            As[r * 36 + c4 + 2] = f2tf32(va.z);                                 \
            As[r * 36 + c4 + 3] = f2tf32(va.w);                                 \
            float4 vb = *(const float4*)(B_PTR + (size_t)r * 128 + k0 + c4);    \
            Bs[r * 36 + c4 + 0] = f2tf32(vb.x);                                 \
            Bs[r * 36 + c4 + 1] = f2tf32(vb.y);                                 \
            Bs[r * 36 + c4 + 2] = f2tf32(vb.z);                                 \
            Bs[r * 36 + c4 + 3] = f2tf32(vb.w);                                 \
        }                                                                       \
        __syncthreads();                                                        \
        _Pragma("unroll")                                                       \
        for (int kk = 0; kk < 32; kk += 8) {                                    \
            uint32_t af[2][4];                                                  \
            _Pragma("unroll")                                                   \
            for (int i = 0; i < 2; i++) {                                       \
                int rbase = (wm * 32 + i * 16 + gr) * 36 + kk + gc;             \
                af[i][0] = As[rbase];                                           \
                af[i][1] = As[rbase + 8 * 36];                                  \
                af[i][2] = As[rbase + 4];                                       \
                af[i][3] = As[rbase + 8 * 36 + 4];                              \
            }                                                                   \
            uint32_t bf[8][2];                                                  \
            _Pragma("unroll")                                                   \
            for (int j = 0; j < 8; j++) {                                       \
                int nbase = (wn * 64 + j * 8 + gr) * 36 + kk + gc;              \
                bf[j][0] = Bs[nbase];                                           \
                bf[j][1] = Bs[nbase + 4];                                       \
            }                                                                   \
            _Pragma("unroll")                                                   \
            for (int i = 0; i < 2; i++)                                         \
                _Pragma("unroll")                                               \
                for (int j = 0; j < 8; j++)                                     \
                    mma_tf32(acc[i][j][0], acc[i][j][1], acc[i][j][2], acc[i][j][3], \
                             af[i][0], af[i][1], af[i][2], af[i][3],            \
                             bf[j][0], bf[j][1]);                               \
        }                                                                       \
        __syncthreads();                                                        \
    }                                                                           \
    EPILOGUE

// ---------------------------------------------------------------------------
// Kernel 1: fused QKV projection -> (B,H,N,D) scatter.  grid = (256, 3)
// ---------------------------------------------------------------------------
__global__ __launch_bounds__(256, 2) void qkv_mma(
    const float* __restrict__ q,
    const float* __restrict__ Wq, const float* __restrict__ bq,
    const float* __restrict__ Wk, const float* __restrict__ bk,
    const float* __restrict__ Wv, const float* __restrict__ bv)
{
    const int which = blockIdx.y;
    const float* __restrict__ Wm = (which == 0) ? Wq : ((which == 1) ? Wk : Wv);
    const float* __restrict__ bm = (which == 0) ? bq : ((which == 1) ? bk : bv);
    float* __restrict__ outp = (which == 0) ? g_Q : ((which == 1) ? g_K : g_V);

    GEMM_MMA_BODY(q, Wm,
    {
        _Pragma("unroll")
        for (int i = 0; i < 2; i++) {
            _Pragma("unroll")
            for (int e2 = 0; e2 < 2; e2++) {
                int m = m0 + wm * 32 + i * 16 + gr + e2 * 8;
                int b = m >> 13;
                int n = m & 8191;
                _Pragma("unroll")
                for (int j = 0; j < 8; j++) {
                    int col = wn * 64 + j * 8 + gc * 2;
                    int h = col >> 5;
                    int d = col & 31;
                    float2 v;
                    v.x = acc[i][j][e2 * 2 + 0] + bm[col];
                    v.y = acc[i][j][e2 * 2 + 1] + bm[col + 1];
                    *(float2*)(outp + ((size_t)(b * Hc + h) * Nc + n) * Dc + d) = v;
                }
            }
        }
    })
}

// ---------------------------------------------------------------------------
// Kernel 3: output projection. out = ctx @ Wo.T + bo -> d_out (B,N,E)
// ---------------------------------------------------------------------------
__global__ __launch_bounds__(256, 2) void out_mma(
    const float* __restrict__ Wo, const float* __restrict__ bo,
    float* __restrict__ outp)
{
    const float* __restrict__ ctxp = g_ctx;
    GEMM_MMA_BODY(ctxp, Wo,
    {
        _Pragma("unroll")
        for (int i = 0; i < 2; i++) {
            _Pragma("unroll")
            for (int e2 = 0; e2 < 2; e2++) {
                int m = m0 + wm * 32 + i * 16 + gr + e2 * 8;
                _Pragma("unroll")
                for (int j = 0; j < 8; j++) {
                    int col = wn * 64 + j * 8 + gc * 2;
                    float2 v;
                    v.x = acc[i][j][e2 * 2 + 0] + bo[col];
                    v.y = acc[i][j][e2 * 2 + 1] + bo[col + 1];
                    *(float2*)(outp + (size_t)m * 128 + col) = v;
                }
            }
        }
    })
}

// ---------------------------------------------------------------------------
// Kernel 2: tensorized sliding-window attention.
// Block = 64 queries of one (b,h). Window keys: 96 rows [n0-16, n0+80).
// S(64x96) = Q @ Kwin^T via split-tf32 MMA (exact scores to ~fp32);
// zero-padded K gives score 0 for OOB keys (matches reference's padding).
// Out-of-band entries predicated to 0 in epilogue -> dense P for PV MMA.
// grid = (N/64, BH), 128 threads (4 warps, warp grid 2M x 2N).
// ---------------------------------------------------------------------------
#define AT 64
#define WK 96
#define QSTR 36
#define KSTR 36
#define VSTR 100
#define SSTR 100

__device__ __forceinline__ uint32_t hi_bits(float x) {
    return __float_as_uint(x) & 0xFFFFE000u;
}

__global__ __launch_bounds__(128) void attn_mma(float* __restrict__ probs_out)
{
    extern __shared__ float sm[];
    float* Ks  = sm;                       // 96 x 36 (raw fp32)
    float* Qs  = Ks + WK * KSTR;           // 64 x 36 (raw fp32)
    float* Vt  = Qs + AT * QSTR;           // 32 x 100 (tf32-rounded, transposed)
    float* Ssm = Vt + 32 * VSTR;           // 64 x 100 (scores -> probs, dense)

    const int tile = blockIdx.x;           // 0..127
    const int bh   = blockIdx.y;           // 0..15
    const int tid  = threadIdx.x;
    const int wid  = tid >> 5;
    const int lane = tid & 31;
    const int wm   = wid >> 1;             // 0..1
    const int wn   = wid & 1;              // 0..1
    const int gr   = lane >> 2;
    const int gc   = lane & 3;
    const int n0   = tile * AT;
    const int g0   = n0 - PADc;

    const float* __restrict__ Qg = g_Q + (size_t)bh * Nc * Dc;
    const float* __restrict__ Kg = g_K + (size_t)bh * Nc * Dc;
    const float* __restrict__ Vg = g_V + (size_t)bh * Nc * Dc;

    // Stage Q tile (64x32 raw fp32)
#pragma unroll
    for (int l = 0; l < 4; l++) {
        int idx = tid + l * 128;           // 0..511
        int r   = idx >> 3;
        int c4  = (idx & 7) * 4;
        float4 v = *(const float4*)(Qg + (size_t)(n0 + r) * 32 + c4);
        *(float4*)&Qs[r * QSTR + c4] = v;
    }
    // Stage K window (96x32 raw, zero OOB) and V transposed (tf32, zero OOB)
#pragma unroll
    for (int l = 0; l < 6; l++) {
        int idx = tid + l * 128;           // 0..767
        int r   = idx >> 3;
        int c4  = (idx & 7) * 4;
        int grow = g0 + r;
        float4 kv = make_float4(0.f, 0.f, 0.f, 0.f);
        float4 vv = make_float4(0.f, 0.f, 0.f, 0.f);
        if (grow >= 0 && grow < Nc) {
            kv = *(const float4*)(Kg + (size_t)grow * 32 + c4);
            vv = *(const float4*)(Vg + (size_t)grow * 32 + c4);
        }
        *(float4*)&Ks[r * KSTR + c4] = kv;
        Vt[(c4 + 0) * VSTR + r] = __uint_as_float(f2tf32(vv.x));
        Vt[(c4 + 1) * VSTR + r] = __uint_as_float(f2tf32(vv.y));
        Vt[(c4 + 2) * VSTR + r] = __uint_as_float(f2tf32(vv.z));
        Vt[(c4 + 3) * VSTR + r] = __uint_as_float(f2tf32(vv.w));
    }
    __syncthreads();

    // ---- QK^T with split-tf32 (hi*hi + hi*lo + lo*hi) ----
    float acc[2][6][4];
#pragma unroll
    for (int i = 0; i < 2; i++)
#pragma unroll
        for (int j = 0; j < 6; j++)
#pragma unroll
            for (int e = 0; e < 4; e++) acc[i][j][e] = 0.f;

#pragma unroll
    for (int kk = 0; kk < 32; kk += 8) {
        uint32_t ah[2][4], al[2][4];
#pragma unroll
        for (int i = 0; i < 2; i++) {
            int base = (wm * 32 + i * 16 + gr) * QSTR + kk + gc;
            float x0 = Qs[base];
            float x1 = Qs[base + 8 * QSTR];
            float x2 = Qs[base + 4];
            float x3 = Qs[base + 8 * QSTR + 4];
            ah[i][0] = hi_bits(x0); al[i][0] = __float_as_uint(x0 - __uint_as_float(ah[i][0]));
            ah[i][1] = hi_bits(x1); al[i][1] = __float_as_uint(x1 - __uint_as_float(ah[i][1]));
            ah[i][2] = hi_bits(x2); al[i][2] = __float_as_uint(x2 - __uint_as_float(ah[i][2]));
            ah[i][3] = hi_bits(x3); al[i][3] = __float_as_uint(x3 - __uint_as_float(ah[i][3]));
        }
        uint32_t bhf[6][2], blf[6][2];
#pragma unroll
        for (int j = 0; j < 6; j++) {
            int nb = (wn * 48 + j * 8 + gr) * KSTR + kk + gc;
            float y0 = Ks[nb];
            float y1 = Ks[nb + 4];
            bhf[j][0] = hi_bits(y0); blf[j][0] = __float_as_uint(y0 - __uint_as_float(bhf[j][0]));
            bhf[j][1] = hi_bits(y1); blf[j][1] = __float_as_uint(y1 - __uint_as_float(bhf[j][1]));
        }
#pragma unroll
        for (int i = 0; i < 2; i++)
#pragma unroll
            for (int j = 0; j < 6; j++) {
                mma_tf32(acc[i][j][0], acc[i][j][1], acc[i][j][2], acc[i][j][3],
                         al[i][0], al[i][1], al[i][2], al[i][3], bhf[j][0], bhf[j][1]);
                mma_tf32(acc[i][j][0], acc[i][j][1], acc[i][j][2], acc[i][j][3],
                         ah[i][0], ah[i][1], ah[i][2], ah[i][3], blf[j][0], blf[j][1]);
                mma_tf32(acc[i][j][0], acc[i][j][1], acc[i][j][2], acc[i][j][3],
                         ah[i][0], ah[i][1], ah[i][2], ah[i][3], bhf[j][0], bhf[j][1]);
            }
    }

    // Epilogue: scale in-band, zero out-of-band (band: c in [m, m+32])
    const float scale = 0.17677669529663687f;   // 1/sqrt(32)
#pragma unroll
    for (int i = 0; i < 2; i++) {
#pragma unroll
        for (int j = 0; j < 6; j++) {
            int c0 = wn * 48 + j * 8 + gc * 2;
#pragma unroll
            for (int e2 = 0; e2 < 2; e2++) {
                int m = wm * 32 + i * 16 + gr + e2 * 8;
                float v0 = (c0     >= m && c0     <= m + 32) ? acc[i][j][e2 * 2 + 0] * scale : 0.f;
                float v1 = (c0 + 1 >= m && c0 + 1 <= m + 32) ? acc[i][j][e2 * 2 + 1] * scale : 0.f;
                float2 v; v.x = v0; v.y = v1;
                *(float2*)&Ssm[m * SSTR + c0] = v;
            }
        }
    }
    __syncthreads();

    // ---- softmax per query (33-wide band; padding scores are exact 0) ----
    if (tid < AT) {
        const int t = tid;
        float sc[33];
#pragma unroll
        for (int w = 0; w < 33; w++) sc[w] = Ssm[t * SSTR + t + w];
        float mx = sc[0];
#pragma unroll
        for (int w = 1; w < 33; w++) mx = fmaxf(mx, sc[w]);
        float ssum = 0.f;
#pragma unroll
        for (int w = 0; w < 33; w++) { sc[w] = __expf(sc[w] - mx); ssum += sc[w]; }
        const float rinv = 1.f / ssum;
        float* __restrict__ pr = probs_out + ((size_t)bh * Nc + n0 + t) * Wc;
#pragma unroll
        for (int w = 0; w < 33; w++) {
            float p = sc[w] * rinv;
            pr[w] = p;
            Ssm[t * SSTR + t + w] = __uint_as_float(f2tf32(p));
        }
    }
    __syncthreads();

    // ---- ctx = P(64x96) @ V(96x32) via tf32 MMA ----
    float acc2[2][2][4];
#pragma unroll
    for (int i = 0; i < 2; i++)
#pragma unroll
        for (int j = 0; j < 2; j++)
#pragma unroll
            for (int e = 0; e < 4; e++) acc2[i][j][e] = 0.f;

#pragma unroll
    for (int kk = 0; kk < 96; kk += 8) {
        uint32_t af[2][4];
#pragma unroll
        for (int i = 0; i < 2; i++) {
            int base = (wm * 32 + i * 16 + gr) * SSTR + kk + gc;
            af[i][0] = __float_as_uint(Ssm[base]);
            af[i][1] = __float_as_uint(Ssm[base + 8 * SSTR]);
            af[i][2] = __float_as_uint(Ssm[base + 4]);
            af[i][3] = __float_as_uint(Ssm[base + 8 * SSTR + 4]);
        }
        uint32_t bf[2][2];
#pragma unroll
        for (int j = 0; j < 2; j++) {
            int nb = (wn * 16 + j * 8 + gr) * VSTR + kk + gc;
            bf[j][0] = __float_as_uint(Vt[nb]);
            bf[j][1] = __float_as_uint(Vt[nb + 4]);
        }
#pragma unroll
        for (int i = 0; i < 2; i++)
#pragma unroll
            for (int j = 0; j < 2; j++)
                mma_tf32(acc2[i][j][0], acc2[i][j][1], acc2[i][j][2], acc2[i][j][3],
                         af[i][0], af[i][1], af[i][2], af[i][3], bf[j][0], bf[j][1]);
    }

    // Epilogue: ctx -> (B,N,E)
    const int b = bh >> 2;
    const int h = bh & 3;
#pragma unroll
    for (int i = 0; i < 2; i++) {
#pragma unroll
        for (int j = 0; j < 2; j++) {
            int d = wn * 16 + j * 8 + gc * 2;
#pragma unroll
            for (int e2 = 0; e2 < 2; e2++) {
                int m = wm * 32 + i * 16 + gr + e2 * 8;
                float2 v;
                v.x = acc2[i][j][e2 * 2 + 0];
                v.y = acc2[i][j][e2 * 2 + 1];
                *(float2*)(g_ctx + ((size_t)(b * Nc) + n0 + m) * Ec + h * 32 + d) = v;
            }
        }
    }
}

// ---------------------------------------------------------------------------
extern "C" void kernel_launch(void* const* d_in, const int* in_sizes, int n_in,
                              void* d_out, int out_size)
{
    (void)in_sizes; (void)n_in; (void)out_size;
    const float* q  = (const float*)d_in[0];
    const float* Wq = (const float*)d_in[1];
    const float* bq = (const float*)d_in[2];
    const float* Wk = (const float*)d_in[3];
    const float* bk = (const float*)d_in[4];
    const float* Wv = (const float*)d_in[5];
    const float* bv = (const float*)d_in[6];
    const float* Wo = (const float*)d_in[7];
    const float* bo = (const float*)d_in[8];

    float* outp  = (float*)d_out;                         // (B,N,E)
    float* probs = outp + (size_t)Bc * Nc * Ec;           // (B,H,N,W)

    const int attn_smem = (WK * KSTR + AT * QSTR + 32 * VSTR + AT * SSTR) * 4; // 61440
    cudaFuncSetAttribute(attn_mma, cudaFuncAttributeMaxDynamicSharedMemorySize, attn_smem);

    qkv_mma<<<dim3(Mc / 128, 3), 256>>>(q, Wq, bq, Wk, bk, Wv, bv);
    attn_mma<<<dim3(Nc / AT, BHc), 128, attn_smem>>>(probs);
    out_mma<<<dim3(Mc / 128, 1), 256>>>(Wo, bo, outp);
}